// round 8
// baseline (speedup 1.0000x reference)
#include <cuda_runtime.h>

// Cost-volume construction:
//   out[0, c,      d, h, w] = imgl[0, c, h, w]                      (broadcast over d)
//   out[0, c + 32, d, h, w] = (w >= d) ? imgr[0, c, h, w - d] : 0
// Shapes: imgl/imgr (1, 32, 256, 480) f32, out (1, 64, 32, 256, 480) f32.
//
// R8: 256-bit stores (sm_10x st.global.v8.f32). Each thread owns 8
// consecutive floats; one STG.256 per (half, disparity) -> warp writes
// 1KB contiguous per instruction (8 FULL 128B sectors; unlike R4's paired
// STG.128 which half-filled sectors per wave). Store instruction count
// halves vs R5. Window: s = w - d0 is a multiple of 8 => all 8 disparity
// windows come from two aligned 8-float loads at s-8 and s, with exact
// per-quad zero predication (aligned quads never straddle the w<d boundary).

constexpr int C  = 32;
constexpr int D  = 32;
constexpr int H2 = 256;
constexpr int W2 = 480;
constexpr int W8 = W2 / 8;              // 60 groups per row
constexpr int PLANE = H2 * W2;          // 122880 floats
constexpr int CH    = D * PLANE;        // 3,932,160 floats per out-channel
constexpr int DSPLIT = 8;               // disparities per thread
constexpr int NSPLIT = D / DSPLIT;      // 4

__device__ __forceinline__ void stg256_cs(float* p, const float* v) {
    asm volatile(
        "st.global.cs.v8.f32 [%0], {%1,%2,%3,%4,%5,%6,%7,%8};"
        :: "l"(p), "f"(v[0]), "f"(v[1]), "f"(v[2]), "f"(v[3]),
           "f"(v[4]), "f"(v[5]), "f"(v[6]), "f"(v[7])
        : "memory");
}

__device__ __forceinline__ void ldg256(float* v, const float* p) {
    asm volatile(
        "ld.global.nc.v8.f32 {%0,%1,%2,%3,%4,%5,%6,%7}, [%8];"
        : "=f"(v[0]), "=f"(v[1]), "=f"(v[2]), "=f"(v[3]),
          "=f"(v[4]), "=f"(v[5]), "=f"(v[6]), "=f"(v[7])
        : "l"(p));
}

__global__ __launch_bounds__(256) void cost_volume_kernel(
    const float* __restrict__ imgl,
    const float* __restrict__ imgr,
    float* __restrict__ out)
{
    int idx = blockIdx.x * blockDim.x + threadIdx.x;

    int w8 = idx % W8;
    int t  = idx / W8;
    int h  = t % H2;
    t /= H2;
    int c     = t % C;
    int split = t / C;                  // 0..3
    int w  = w8 * 8;
    int d0 = split * DSPLIT;

    // ---- Left operand: 8 floats, broadcast over DSPLIT disparities ----
    float l[8];
    ldg256(l, imgl + c * PLANE + h * W2 + w);

    // ---- Right operand: 16-float register window from 2 aligned v8 loads ----
    const float* rrow = imgr + c * PLANE + h * W2;
    int s = w - d0;                     // multiple of 8, s >= -24

    float arr[16];
    if (s - 8 >= 0) ldg256(arr, rrow + s - 8);
    else {
#pragma unroll
        for (int j = 0; j < 8; ++j) arr[j] = 0.0f;
    }
    if (s >= 0) ldg256(arr + 8, rrow + s);
    else {
#pragma unroll
        for (int j = 0; j < 8; ++j) arr[8 + j] = 0.0f;
    }

    float* outL = out + c * CH       + d0 * PLANE + h * W2 + w;
    float* outR = out + (c + C) * CH + d0 * PLANE + h * W2 + w;

    // interleaved stores: both write streams active every iteration
#pragma unroll
    for (int i = 0; i < DSPLIT; ++i) {
        float r[8];
#pragma unroll
        for (int j = 0; j < 8; ++j) r[j] = arr[8 - i + j];
        stg256_cs(outL + i * PLANE, l);
        stg256_cs(outR + i * PLANE, r);
    }
}

extern "C" void kernel_launch(void* const* d_in, const int* in_sizes, int n_in,
                              void* d_out, int out_size)
{
    const float* imgl = (const float*)d_in[0];
    const float* imgr = (const float*)d_in[1];
    float* out = (float*)d_out;

    const int total = NSPLIT * C * H2 * W8;          // 1,966,080 threads
    const int block = 256;
    const int grid  = (total + block - 1) / block;   // 7680 blocks
    cost_volume_kernel<<<grid, block>>>(imgl, imgr, out);
}